// round 10
// baseline (speedup 1.0000x reference)
#include <cuda_runtime.h>

// B=4, T=32, C=512, ENC=32, DIM=1024, N_PAIRS=4096
// Output: Re(final_state), float32[4194304], idx = P*1024 + d.

typedef unsigned long long ull;

__device__ float2 g_aL[128 * 32];
__device__ float2 g_bL[128 * 32];

__device__ __forceinline__ ull pk2(float lo, float hi) {
    ull r; asm("mov.b64 %0, {%1, %2};" : "=l"(r) : "f"(lo), "f"(hi)); return r;
}
__device__ __forceinline__ void unpk2(ull v, float& lo, float& hi) {
    asm("mov.b64 {%0, %1}, %2;" : "=f"(lo), "=f"(hi) : "l"(v));
}
__device__ __forceinline__ ull fma2(ull a, ull b, ull c) {
    ull d; asm("fma.rn.f32x2 %0, %1, %2, %3;" : "=l"(d) : "l"(a), "l"(b), "l"(c)); return d;
}

// Complex 2x2 gate G = RY(ty)*RX(tx) as a shfl butterfly inside one warp.
__device__ __forceinline__ float2 gate_shfl_c(float2 v, int lane, int mask,
                                              float tx, float ty) {
    float cx, sx, cy, sy;
    sincosf(0.5f * tx, &sx, &cx);
    sincosf(0.5f * ty, &sy, &cy);
    float ox = __shfl_xor_sync(0xffffffffu, v.x, mask);
    float oy = __shfl_xor_sync(0xffffffffu, v.y, mask);
    bool hi = (lane & mask) != 0;
    float mdx = cy * cx,                 mdy = hi ? -sy * sx : sy * sx;
    float mox = hi ? sy * cx : -sy * cx, moy = -cy * sx;
    float2 r;
    r.x = mdx * v.x - mdy * v.y + mox * ox - moy * oy;
    r.y = mdx * v.y + mdy * v.x + mox * oy + moy * ox;
    return r;
}

// enc = L2norm(x @ W^T + b); then layer-1 gates -> a' (wires 0..4), b' (5..9).
__global__ void __launch_bounds__(256) enc_kernel(
    const float* __restrict__ x, const float* __restrict__ W,
    const float* __restrict__ bias, const float* __restrict__ trx,
    const float* __restrict__ try0) {
    int row = blockIdx.x;            // 0..127
    __shared__ float part[32][8];
    int tid = threadIdx.x;
    int j = tid >> 3, p = tid & 7;
    const float4* xr = (const float4*)(x + row * 512 + p * 64);
    const float4* wr = (const float4*)(W + j * 512 + p * 64);
    float s = 0.f;
#pragma unroll
    for (int k = 0; k < 16; k++) {
        float4 xv = xr[k], wv = wr[k];
        s = fmaf(xv.x, wv.x, s); s = fmaf(xv.y, wv.y, s);
        s = fmaf(xv.z, wv.z, s); s = fmaf(xv.w, wv.w, s);
    }
    part[j][p] = s;
    __syncthreads();
    if (tid < 32) {
        int lane = tid;
        float acc = bias[lane];
#pragma unroll
        for (int q = 0; q < 8; q++) acc += part[lane][q];
        float sq = acc * acc;
#pragma unroll
        for (int o = 16; o; o >>= 1) sq += __shfl_xor_sync(0xffffffffu, sq, o);
        float v = acc * rsqrtf(sq);
        float2 a = make_float2(v, 0.f);
        float2 b = make_float2(v, 0.f);
#pragma unroll
        for (int w = 0; w < 5; w++) {
            int mask = 16 >> w;      // wire w -> bit (4-w)
            a = gate_shfl_c(a, lane, mask, trx[w], try0[w]);
            b = gate_shfl_c(b, lane, mask, trx[w + 5], try0[w + 5]);
        }
        int gi = row * 32 + lane;
        g_aL[gi] = a;
        g_bL[gi] = b;
    }
}

// Pair kernel v3: two pairs per warp via f32x2; tangent-form butterflies
// (scale C = prod cos folded into a at load); NO cross-lane shuffles —
// wires 0..4 in-thread, one XOR-swizzled smem transpose, wires 5..9
// in-thread, then STG.128 stores (each thread owns 32 consecutive floats).
__global__ void __launch_bounds__(128) pair_kernel(
    const float* __restrict__ try1, float* __restrict__ out,
    unsigned int n_out_f32) {
    __shared__ float2 a_s[32];          // a-row for block (scaled by C)
    __shared__ float4 bpair[4][32];     // per warp: {bj0.re,bj0.im,bj1.re,bj1.im}
    __shared__ float csm[10], tsm[10];
    __shared__ ull tr[4][32 * 32];      // per-warp transpose tile (8KB each)
    int tid = threadIdx.x, wid = tid >> 5, lane = tid & 31;

    int Pbase = blockIdx.x * 8;
    int bb = Pbase >> 10;
    int rest = Pbase & 1023;
    int i = rest >> 5;                  // a-row, same for whole block
    int jb = rest & 31;

    if (tid < 10) {
        float c, s;
        sincosf(0.5f * try1[tid], &s, &c);
        csm[tid] = c;
        tsm[tid] = s / c;
    }
    {   // b rows for this warp's two pairs
        int j0 = jb + 2 * wid;
        float2 b0 = g_bL[(bb * 32 + j0) * 32 + lane];
        float2 b1 = g_bL[(bb * 32 + j0 + 1) * 32 + lane];
        bpair[wid][lane] = make_float4(b0.x, b0.y, b1.x, b1.y);
    }
    __syncthreads();
    if (tid < 32) {
        float C = csm[0];
#pragma unroll
        for (int k = 1; k < 10; k++) C *= csm[k];
        float2 av = g_aL[(bb * 32 + i) * 32 + tid];
        a_s[tid] = make_float2(av.x * C, av.y * C);
    }
    __syncthreads();

    float tv[10];
#pragma unroll
    for (int k = 0; k < 10; k++) tv[k] = tsm[k];

    // Permutation e(d) is GF(2)-linear: e = lp(lane) ^ mp(m), d = (m<<5)|lane.
    int lp = ((lane ^ (lane >> 1)) & 0xF) | (lane & 16) | ((lane & 1) * 0x300);

    ull wv[32];
#pragma unroll
    for (int m = 0; m < 32; m++) {
        const int mp = ((m & 1) << 4) | ((m ^ (m >> 1)) << 5);
        int e = lp ^ mp;
        float2 a = a_s[e >> 5];
        float4 b4 = bpair[wid][e & 31];
        wv[m] = pk2(a.x * b4.x - a.y * b4.y,    // pair A: Re(a'*b_j0')
                    a.x * b4.z - a.y * b4.w);   // pair B: Re(a'*b_j1')
    }

    // Wires 0..4: in-thread t-form butterflies over bit (4-w) of m.
#pragma unroll
    for (int w = 0; w < 5; w++) {
        float t = tv[w];
        ull tp = pk2(t, t), ntp = pk2(-t, -t);
        const int mask = 16 >> w;
#pragma unroll
        for (int m0 = 0; m0 < 32; m0++) {
            if (m0 & mask) continue;
            int m1 = m0 | mask;
            ull v0 = wv[m0], v1 = wv[m1];
            wv[m0] = fma2(ntp, v1, v0);   // v0 - t*v1
            wv[m1] = fma2(tp, v0, v1);    // v1 + t*v0
        }
    }

    // Transpose the 32x32 (lane x reg) tile through smem, XOR-swizzled so
    // both store and load are bank-conflict-free.
    // Store: thread L, reg M -> tr[L*32 + (M^L)]  (element d=(M<<5)|L)
    // Load : thread t, reg r <- tr[r*32 + (t^r)]  (element d=(t<<5)|r)
    ull* tw = tr[wid];
#pragma unroll
    for (int m = 0; m < 32; m++) tw[(lane << 5) | (m ^ lane)] = wv[m];
    __syncwarp();
#pragma unroll
    for (int r = 0; r < 32; r++) wv[r] = tw[(r << 5) | (lane ^ r)];

    // Wires 5..9: now ALSO in-thread, over bit (4-w) of r (d bits 4..0 = r).
#pragma unroll
    for (int w = 0; w < 5; w++) {
        float t = tv[5 + w];
        ull tp = pk2(t, t), ntp = pk2(-t, -t);
        const int mask = 16 >> w;
#pragma unroll
        for (int r0 = 0; r0 < 32; r0++) {
            if (r0 & mask) continue;
            int r1 = r0 | mask;
            ull v0 = wv[r0], v1 = wv[r1];
            wv[r0] = fma2(ntp, v1, v0);
            wv[r1] = fma2(tp, v0, v1);
        }
    }

    // Thread `lane` holds d = lane*32 + r (r = 0..31): 32 consecutive floats
    // per pair. Vectorized stores.
    int P0 = Pbase + 2 * wid;
    float* opA = out + (size_t)P0 * 1024 + lane * 32;
    float* opB = opA + 1024;
    if ((unsigned int)(P0 + 2) * 1024u <= n_out_f32) {
#pragma unroll
        for (int q = 0; q < 8; q++) {
            float l0, h0, l1, h1, l2, h2, l3, h3;
            unpk2(wv[4 * q], l0, h0);     unpk2(wv[4 * q + 1], l1, h1);
            unpk2(wv[4 * q + 2], l2, h2); unpk2(wv[4 * q + 3], l3, h3);
            ((float4*)opA)[q] = make_float4(l0, l1, l2, l3);
            ((float4*)opB)[q] = make_float4(h0, h1, h2, h3);
        }
    } else {
        unsigned int baseA = (unsigned int)P0 * 1024u + (unsigned int)(lane * 32);
#pragma unroll
        for (int r = 0; r < 32; r++) {
            float lo, hi; unpk2(wv[r], lo, hi);
            if (baseA + r < n_out_f32) opA[r] = lo;
            if (baseA + r + 1024u < n_out_f32) opB[r] = hi;
        }
    }
}

__global__ void zero_kernel(float* out, unsigned int n_floats) {
    unsigned int i = blockIdx.x * blockDim.x + threadIdx.x;
    if (i < n_floats) out[i] = 0.f;
}

extern "C" void kernel_launch(void* const* d_in, const int* in_sizes, int n_in,
                              void* d_out, int out_size) {
    long mx = 0;
    for (int i = 0; i < n_in; i++) if (in_sizes[i] > mx) mx = in_sizes[i];
    int div = (mx == 262144) ? 4 : 1;

    const float* x = 0; const float* W = 0; const float* bias = 0;
    const float* th[3] = {0, 0, 0};
    int nth = 0;
    for (int i = 0; i < n_in; i++) {
        long s = in_sizes[i] / div;
        const float* p = (const float*)d_in[i];
        if (s == 65536)      x = p;
        else if (s == 16384) W = p;
        else if (s == 32)    bias = p;
        else if (s == 10 && nth < 3) th[nth++] = p;
    }
    if (!x || !W || !bias || nth < 3) {
        if (n_in >= 6) {
            x = (const float*)d_in[0]; W = (const float*)d_in[1];
            bias = (const float*)d_in[2];
            th[0] = (const float*)d_in[3]; th[1] = (const float*)d_in[4];
            th[2] = (const float*)d_in[5];
        } else {
            zero_kernel<<<(out_size + 255) / 256, 256>>>((float*)d_out,
                                                         (unsigned int)out_size);
            return;
        }
    }

    enc_kernel<<<128, 256>>>(x, W, bias, th[0], th[1]);
    pair_kernel<<<512, 128>>>(th[2], (float*)d_out, (unsigned int)out_size);
}

// round 11
// speedup vs baseline: 1.7538x; 1.7538x over previous
#include <cuda_runtime.h>

// B=4, T=32, C=512, ENC=32, DIM=1024, N_PAIRS=4096
// Output: Re(final_state), float32[4194304], idx = P*1024 + da'*32 + db'.
//
// Factorization: CNOT-ring perm is GF(2)-linear with near-block structure:
//   e_a = gray5(da) ^ 24*(db&1),  e_b = gray5(db) ^ 16*(da&1)
// => out = sum over parities (pa,pb) of [YA.a-vec] (x) [YB.b-vec], rank-8 real
// (re/im split, -1 on im(x)im folded into A). Pair kernel = dot-8 per element.

__device__ float g_A[128][32][8];   // [row][da'][k]: k0..3 = Are(2pa+pb), k4..7 = -Aim
__device__ float g_B[128][32][8];   // [row][db'][k]: k0..3 = Bre at 2pa+pb,  k4..7 = +Bim

// Complex 2x2 gate G = RY(ty)*RX(tx) as a shfl butterfly inside one warp.
__device__ __forceinline__ float2 gate_shfl_c(float2 v, int lane, int mask,
                                              float tx, float ty) {
    float cx, sx, cy, sy;
    sincosf(0.5f * tx, &sx, &cx);
    sincosf(0.5f * ty, &sy, &cy);
    float ox = __shfl_xor_sync(0xffffffffu, v.x, mask);
    float oy = __shfl_xor_sync(0xffffffffu, v.y, mask);
    bool hi = (lane & mask) != 0;
    float mdx = cy * cx,                 mdy = hi ? -sy * sx : sy * sx;
    float mox = hi ? sy * cx : -sy * cx, moy = -cy * sx;
    float2 r;
    r.x = mdx * v.x - mdy * v.y + mox * ox - moy * oy;
    r.y = mdx * v.y + mdy * v.x + mox * oy + moy * ox;
    return r;
}

// Real RY butterfly round over `mask` for a complex (re,im) pair in regs.
__device__ __forceinline__ void ry_round(float& ur, float& ui, int lane,
                                         int mask, float c, float s) {
    float orr = __shfl_xor_sync(0xffffffffu, ur, mask);
    float oi  = __shfl_xor_sync(0xffffffffu, ui, mask);
    if (lane & mask) {           // new1 = s*u0 + c*u1
        ur = fmaf(s, orr,  c * ur);
        ui = fmaf(s, oi,   c * ui);
    } else {                     // new0 = c*u0 - s*u1
        ur = fmaf(-s, orr, c * ur);
        ui = fmaf(-s, oi,  c * ui);
    }
}

// enc = L2norm(x @ W^T + b); layer-1 gates; then build the 8 rank-factors
// per row for each side (A: wires 0..4 thetas; B: wires 5..9 thetas).
__global__ void __launch_bounds__(256) enc_kernel(
    const float* __restrict__ x, const float* __restrict__ W,
    const float* __restrict__ bias, const float* __restrict__ trx,
    const float* __restrict__ try0, const float* __restrict__ try1) {
    int row = blockIdx.x;            // 0..127
    __shared__ float part[32][8];
    int tid = threadIdx.x;
    int j = tid >> 3, p = tid & 7;
    const float4* xr = (const float4*)(x + row * 512 + p * 64);
    const float4* wr = (const float4*)(W + j * 512 + p * 64);
    float s = 0.f;
#pragma unroll
    for (int k = 0; k < 16; k++) {
        float4 xv = xr[k], wv = wr[k];
        s = fmaf(xv.x, wv.x, s); s = fmaf(xv.y, wv.y, s);
        s = fmaf(xv.z, wv.z, s); s = fmaf(xv.w, wv.w, s);
    }
    part[j][p] = s;
    __syncthreads();
    if (tid < 32) {
        int lane = tid;
        float acc = bias[lane];
#pragma unroll
        for (int q = 0; q < 8; q++) acc += part[lane][q];
        float sq = acc * acc;
#pragma unroll
        for (int o = 16; o; o >>= 1) sq += __shfl_xor_sync(0xffffffffu, sq, o);
        float v = acc * rsqrtf(sq);
        float2 a = make_float2(v, 0.f);
        float2 b = make_float2(v, 0.f);
#pragma unroll
        for (int w = 0; w < 5; w++) {
            int mask = 16 >> w;      // wire w -> bit (4-w)
            a = gate_shfl_c(a, lane, mask, trx[w], try0[w]);
            b = gate_shfl_c(b, lane, mask, trx[w + 5], try0[w + 5]);
        }

        // Final-layer RY coefficients.
        float cA[5], sA[5], cB[5], sB[5];
#pragma unroll
        for (int w = 0; w < 5; w++) {
            sincosf(0.5f * try1[w], &sA[w], &cA[w]);
            sincosf(0.5f * try1[w + 5], &sB[w], &cB[w]);
        }
        int gray = lane ^ (lane >> 1);   // 5-bit gray (bit4 == lane bit4)

        // A-side factors: A[sel=pa][off=pb] = YA * (parity-masked gray-perm a)
#pragma unroll
        for (int sel = 0; sel < 2; sel++) {
#pragma unroll
            for (int off = 0; off < 2; off++) {
                int src = gray ^ (off ? 24 : 0);
                float ur = __shfl_sync(0xffffffffu, a.x, src);
                float ui = __shfl_sync(0xffffffffu, a.y, src);
                if ((lane & 1) != sel) { ur = 0.f; ui = 0.f; }
#pragma unroll
                for (int w = 0; w < 5; w++)
                    ry_round(ur, ui, lane, 16 >> w, cA[w], sA[w]);
                int k = 2 * sel + off;
                g_A[row][lane][k] = ur;
                g_A[row][lane][4 + k] = -ui;   // fold the im(x)im minus sign
            }
        }
        // B-side factors: B[sel=pb][off=pa], stored at slot k = 2*off+sel
#pragma unroll
        for (int sel = 0; sel < 2; sel++) {
#pragma unroll
            for (int off = 0; off < 2; off++) {
                int src = gray ^ (off ? 16 : 0);
                float ur = __shfl_sync(0xffffffffu, b.x, src);
                float ui = __shfl_sync(0xffffffffu, b.y, src);
                if ((lane & 1) != sel) { ur = 0.f; ui = 0.f; }
#pragma unroll
                for (int w = 0; w < 5; w++)
                    ry_round(ur, ui, lane, 16 >> w, cB[w], sB[w]);
                int k = 2 * off + sel;
                g_B[row][lane][k] = ur;
                g_B[row][lane][4 + k] = ui;
            }
        }
    }
}

// Pair kernel v4: pure rank-8 outer-product accumulation. One warp per pair,
// 4 pairs (same a-row) per 128-thread block. No shuffles, no butterflies.
__global__ void __launch_bounds__(128) pair_kernel(
    float* __restrict__ out, unsigned int n_out_f32) {
    __shared__ float4 As[64];            // A factors of row i: [da'][re4|im4]
    int tid = threadIdx.x, wid = tid >> 5, lane = tid & 31;
    int P0 = blockIdx.x * 4;
    int bb = P0 >> 10;
    int i = (P0 >> 5) & 31;
    int jb = P0 & 31;                    // multiple of 4
    int rowA = bb * 32 + i;
    if (tid < 64) As[tid] = ((const float4*)g_A[rowA])[tid];

    int rowB = bb * 32 + (jb + wid);
    const float4* bp = (const float4*)g_B[rowB] + lane * 2;
    float4 br = bp[0], bi = bp[1];
    __syncthreads();

    int P = P0 + wid;
    float* op = out + (size_t)P * 1024 + lane;
    bool full = ((unsigned int)(P0 + 4) * 1024u <= n_out_f32);
    if (full) {
#pragma unroll
        for (int m = 0; m < 32; m++) {
            float4 ar = As[2 * m], ai = As[2 * m + 1];
            float acc = ar.x * br.x;
            acc = fmaf(ar.y, br.y, acc);
            acc = fmaf(ar.z, br.z, acc);
            acc = fmaf(ar.w, br.w, acc);
            acc = fmaf(ai.x, bi.x, acc);
            acc = fmaf(ai.y, bi.y, acc);
            acc = fmaf(ai.z, bi.z, acc);
            acc = fmaf(ai.w, bi.w, acc);
            op[m << 5] = acc;
        }
    } else {
        unsigned int base = (unsigned int)P * 1024u + (unsigned int)lane;
#pragma unroll
        for (int m = 0; m < 32; m++) {
            float4 ar = As[2 * m], ai = As[2 * m + 1];
            float acc = ar.x * br.x + ar.y * br.y + ar.z * br.z + ar.w * br.w
                      + ai.x * bi.x + ai.y * bi.y + ai.z * bi.z + ai.w * bi.w;
            if (base + (unsigned int)(m << 5) < n_out_f32) op[m << 5] = acc;
        }
    }
}

__global__ void zero_kernel(float* out, unsigned int n_floats) {
    unsigned int i = blockIdx.x * blockDim.x + threadIdx.x;
    if (i < n_floats) out[i] = 0.f;
}

extern "C" void kernel_launch(void* const* d_in, const int* in_sizes, int n_in,
                              void* d_out, int out_size) {
    long mx = 0;
    for (int i = 0; i < n_in; i++) if (in_sizes[i] > mx) mx = in_sizes[i];
    int div = (mx == 262144) ? 4 : 1;

    const float* x = 0; const float* W = 0; const float* bias = 0;
    const float* th[3] = {0, 0, 0};
    int nth = 0;
    for (int i = 0; i < n_in; i++) {
        long s = in_sizes[i] / div;
        const float* p = (const float*)d_in[i];
        if (s == 65536)      x = p;
        else if (s == 16384) W = p;
        else if (s == 32)    bias = p;
        else if (s == 10 && nth < 3) th[nth++] = p;
    }
    if (!x || !W || !bias || nth < 3) {
        if (n_in >= 6) {
            x = (const float*)d_in[0]; W = (const float*)d_in[1];
            bias = (const float*)d_in[2];
            th[0] = (const float*)d_in[3]; th[1] = (const float*)d_in[4];
            th[2] = (const float*)d_in[5];
        } else {
            zero_kernel<<<(out_size + 255) / 256, 256>>>((float*)d_out,
                                                         (unsigned int)out_size);
            return;
        }
    }

    enc_kernel<<<128, 256>>>(x, W, bias, th[0], th[1], th[2]);
    pair_kernel<<<1024, 128>>>((float*)d_out, (unsigned int)out_size);
}

// round 12
// speedup vs baseline: 2.0273x; 1.1559x over previous
#include <cuda_runtime.h>

// B=4, T=32, C=512, ENC=32, DIM=1024, N_PAIRS=4096
// Output: Re(final_state), float32[4194304], idx = P*1024 + da'*32 + db'.
//
// Factorization: CNOT-ring perm is GF(2)-linear with near-block structure:
//   e_a = gray5(da) ^ 24*(db&1),  e_b = gray5(db) ^ 16*(da&1)
// => out = sum over parities (pa,pb) of [YA.a-vec] (x) [YB.b-vec], rank-8 real
// (re/im split, -1 on im(x)im folded into A). Pair kernel = dot-8 per element.

__device__ float g_A[128][32][8];   // [row][da'][k]: k0..3 = Are(2pa+pb), k4..7 = -Aim
__device__ float g_B[128][32][8];   // [row][db'][k]: k0..3 = Bre at 2pa+pb,  k4..7 = +Bim

// Complex 2x2 gate G = RY(ty)*RX(tx) as a shfl butterfly inside one warp.
__device__ __forceinline__ float2 gate_shfl_c(float2 v, int lane, int mask,
                                              float tx, float ty) {
    float cx, sx, cy, sy;
    sincosf(0.5f * tx, &sx, &cx);
    sincosf(0.5f * ty, &sy, &cy);
    float ox = __shfl_xor_sync(0xffffffffu, v.x, mask);
    float oy = __shfl_xor_sync(0xffffffffu, v.y, mask);
    bool hi = (lane & mask) != 0;
    float mdx = cy * cx,                 mdy = hi ? -sy * sx : sy * sx;
    float mox = hi ? sy * cx : -sy * cx, moy = -cy * sx;
    float2 r;
    r.x = mdx * v.x - mdy * v.y + mox * ox - moy * oy;
    r.y = mdx * v.y + mdy * v.x + mox * oy + moy * ox;
    return r;
}

// Real RY butterfly round over `mask` for a complex (re,im) pair in regs.
__device__ __forceinline__ void ry_round(float& ur, float& ui, int lane,
                                         int mask, float c, float s) {
    float orr = __shfl_xor_sync(0xffffffffu, ur, mask);
    float oi  = __shfl_xor_sync(0xffffffffu, ui, mask);
    if (lane & mask) {           // new1 = s*u0 + c*u1
        ur = fmaf(s, orr,  c * ur);
        ui = fmaf(s, oi,   c * ui);
    } else {                     // new0 = c*u0 - s*u1
        ur = fmaf(-s, orr, c * ur);
        ui = fmaf(-s, oi,  c * ui);
    }
}

// enc = L2norm(x @ W^T + b); layer-1 gates; then the 8 rank-factors per row,
// with the 8 (side,sel,off) factor chains spread across 8 warps.
__global__ void __launch_bounds__(256) enc_kernel(
    const float* __restrict__ x, const float* __restrict__ W,
    const float* __restrict__ bias, const float* __restrict__ trx,
    const float* __restrict__ try0, const float* __restrict__ try1) {
    int row = blockIdx.x;            // 0..127
    __shared__ float part[32][8];
    __shared__ float2 a_sh[32], b_sh[32];
    int tid = threadIdx.x, wid = tid >> 5, lane = tid & 31;
    int j = tid >> 3, p = tid & 7;
    const float4* xr = (const float4*)(x + row * 512 + p * 64);
    const float4* wr = (const float4*)(W + j * 512 + p * 64);
    float s = 0.f;
#pragma unroll
    for (int k = 0; k < 16; k++) {
        float4 xv = xr[k], wv = wr[k];
        s = fmaf(xv.x, wv.x, s); s = fmaf(xv.y, wv.y, s);
        s = fmaf(xv.z, wv.z, s); s = fmaf(xv.w, wv.w, s);
    }
    part[j][p] = s;
    __syncthreads();

    // Warps 0 and 1 independently reduce + apply layer-1 gates (a / b side).
    if (wid < 2) {
        float acc = bias[lane];
#pragma unroll
        for (int q = 0; q < 8; q++) acc += part[lane][q];
        float sq = acc * acc;
#pragma unroll
        for (int o = 16; o; o >>= 1) sq += __shfl_xor_sync(0xffffffffu, sq, o);
        float v = acc * rsqrtf(sq);
        float2 u = make_float2(v, 0.f);
        int toff = (wid == 0) ? 0 : 5;
#pragma unroll
        for (int w = 0; w < 5; w++)
            u = gate_shfl_c(u, lane, 16 >> w, trx[w + toff], try0[w + toff]);
        if (wid == 0) a_sh[lane] = u; else b_sh[lane] = u;
    }
    __syncthreads();

    // 8 warps: one factor-combo each.  wid bit2 = side (0=A,1=B),
    // bit1 = sel (parity), bit0 = off (other-side parity XOR).
    {
        int side = (wid >> 2) & 1, sel = (wid >> 1) & 1, off = wid & 1;
        float cw[5], sw[5];
#pragma unroll
        for (int w = 0; w < 5; w++)
            sincosf(0.5f * try1[w + 5 * side], &sw[w], &cw[w]);
        int gray = lane ^ (lane >> 1);
        int xorv = off ? (side ? 16 : 24) : 0;
        int src = gray ^ xorv;
        float2 uin = side ? b_sh[src] : a_sh[src];
        float ur = uin.x, ui = uin.y;
        if ((lane & 1) != sel) { ur = 0.f; ui = 0.f; }
#pragma unroll
        for (int w = 0; w < 5; w++)
            ry_round(ur, ui, lane, 16 >> w, cw[w], sw[w]);
        if (side == 0) {
            int k = 2 * sel + off;
            g_A[row][lane][k] = ur;
            g_A[row][lane][4 + k] = -ui;   // fold im(x)im minus sign
        } else {
            int k = 2 * off + sel;
            g_B[row][lane][k] = ur;
            g_B[row][lane][4 + k] = ui;
        }
    }
}

// Pair kernel v5: rank-8 dot per element; 2 pairs per 128-thread block,
// 2 warps per pair (16 output rows each) -> 8192 warps for latency hiding.
__global__ void __launch_bounds__(128) pair_kernel(
    float* __restrict__ out, unsigned int n_out_f32) {
    __shared__ float4 As[64];            // A factors of row i: [da'][re4|im4]
    int tid = threadIdx.x, wid = tid >> 5, lane = tid & 31;
    int P0 = blockIdx.x * 2;
    int bb = P0 >> 10;
    int i = (P0 >> 5) & 31;
    int jb = P0 & 31;                    // multiple of 2
    int rowA = bb * 32 + i;
    if (tid < 64) As[tid] = ((const float4*)g_A[rowA])[tid];

    int pj = wid >> 1;                   // which pair (0/1)
    int mh = wid & 1;                    // which half of the 32 output rows
    int rowB = bb * 32 + (jb + pj);
    const float4* bp = (const float4*)g_B[rowB] + lane * 2;
    float4 br = bp[0], bi = bp[1];
    __syncthreads();

    int P = P0 + pj;
    float* op = out + (size_t)P * 1024 + (mh << 9) + lane;
    bool full = ((unsigned int)(P0 + 2) * 1024u <= n_out_f32);
    if (full) {
#pragma unroll
        for (int mm = 0; mm < 16; mm++) {
            int m = (mh << 4) + mm;
            float4 ar = As[2 * m], ai = As[2 * m + 1];
            float acc0 = ar.x * br.x;
            float acc1 = ai.x * bi.x;
            acc0 = fmaf(ar.y, br.y, acc0);
            acc1 = fmaf(ai.y, bi.y, acc1);
            acc0 = fmaf(ar.z, br.z, acc0);
            acc1 = fmaf(ai.z, bi.z, acc1);
            acc0 = fmaf(ar.w, br.w, acc0);
            acc1 = fmaf(ai.w, bi.w, acc1);
            op[mm << 5] = acc0 + acc1;
        }
    } else {
        unsigned int base = (unsigned int)P * 1024u
                          + (unsigned int)((mh << 9) + lane);
#pragma unroll
        for (int mm = 0; mm < 16; mm++) {
            int m = (mh << 4) + mm;
            float4 ar = As[2 * m], ai = As[2 * m + 1];
            float acc = ar.x * br.x + ar.y * br.y + ar.z * br.z + ar.w * br.w
                      + ai.x * bi.x + ai.y * bi.y + ai.z * bi.z + ai.w * bi.w;
            if (base + (unsigned int)(mm << 5) < n_out_f32) op[mm << 5] = acc;
        }
    }
}

__global__ void zero_kernel(float* out, unsigned int n_floats) {
    unsigned int i = blockIdx.x * blockDim.x + threadIdx.x;
    if (i < n_floats) out[i] = 0.f;
}

extern "C" void kernel_launch(void* const* d_in, const int* in_sizes, int n_in,
                              void* d_out, int out_size) {
    long mx = 0;
    for (int i = 0; i < n_in; i++) if (in_sizes[i] > mx) mx = in_sizes[i];
    int div = (mx == 262144) ? 4 : 1;

    const float* x = 0; const float* W = 0; const float* bias = 0;
    const float* th[3] = {0, 0, 0};
    int nth = 0;
    for (int i = 0; i < n_in; i++) {
        long s = in_sizes[i] / div;
        const float* p = (const float*)d_in[i];
        if (s == 65536)      x = p;
        else if (s == 16384) W = p;
        else if (s == 32)    bias = p;
        else if (s == 10 && nth < 3) th[nth++] = p;
    }
    if (!x || !W || !bias || nth < 3) {
        if (n_in >= 6) {
            x = (const float*)d_in[0]; W = (const float*)d_in[1];
            bias = (const float*)d_in[2];
            th[0] = (const float*)d_in[3]; th[1] = (const float*)d_in[4];
            th[2] = (const float*)d_in[5];
        } else {
            zero_kernel<<<(out_size + 255) / 256, 256>>>((float*)d_out,
                                                         (unsigned int)out_size);
            return;
        }
    }

    enc_kernel<<<128, 256>>>(x, W, bias, th[0], th[1], th[2]);
    pair_kernel<<<2048, 128>>>((float*)d_out, (unsigned int)out_size);
}